// round 16
// baseline (speedup 1.0000x reference)
#include <cuda_runtime.h>
#include <cuda_fp16.h>
#include <cstdint>
#include <math.h>

#define B_ 8
#define S_ 2048
#define D_ 256
#define H_ 4
#define DH_ 64

#define QKV_ELEMS ((size_t)B_ * H_ * S_ * DH_)
#define CTX_ELEMS ((size_t)B_ * S_ * D_)

// Scratch (allocation-free rule: __device__ globals)
__device__ __half g_q16h[QKV_ELEMS];   // [b,h,s,dh], pre-scaled by log2e/8
__device__ __half g_k16h[QKV_ELEMS];   // [b,h,s,dh]
__device__ __half g_v16h[QKV_ELEMS];   // [b,h,s,dh]  (ldsm.trans in attention)
__device__ __half g_ctxh[CTX_ELEMS];   // [b*s, 256]  (single fp16)
__device__ __half g_w16h[4 * 256 * 256];  // [mat][n][k] transposed, mats: q,k,v,o
__device__ __half g_w16l[4 * 256 * 256];

// ---------------------------------------------------------------------------
// helpers
// ---------------------------------------------------------------------------
__device__ __forceinline__ uint32_t smem_u32(const void* p) {
    uint32_t a;
    asm("{ .reg .u64 t; cvta.to.shared.u64 t, %1; cvt.u32.u64 %0, t; }"
        : "=r"(a) : "l"(p));
    return a;
}
__device__ __forceinline__ uint32_t swz128(uint32_t x) {
    return x ^ ((x >> 3) & 0x70);
}
__device__ __forceinline__ void ldsm_x4(uint32_t* r, uint32_t addr) {
    asm volatile("ldmatrix.sync.aligned.m8n8.x4.shared.b16 {%0,%1,%2,%3}, [%4];"
                 : "=r"(r[0]), "=r"(r[1]), "=r"(r[2]), "=r"(r[3]) : "r"(addr));
}
__device__ __forceinline__ void ldsm_x4t(uint32_t* r, uint32_t addr) {
    asm volatile("ldmatrix.sync.aligned.m8n8.x4.trans.shared.b16 {%0,%1,%2,%3}, [%4];"
                 : "=r"(r[0]), "=r"(r[1]), "=r"(r[2]), "=r"(r[3]) : "r"(addr));
}
__device__ __forceinline__ void mma16816(float* c, const uint32_t* a, const uint32_t* b) {
    asm volatile("mma.sync.aligned.m16n8k16.row.col.f32.f16.f16.f32 "
                 "{%0,%1,%2,%3}, {%4,%5,%6,%7}, {%8,%9}, {%0,%1,%2,%3};"
                 : "+f"(c[0]), "+f"(c[1]), "+f"(c[2]), "+f"(c[3])
                 : "r"(a[0]), "r"(a[1]), "r"(a[2]), "r"(a[3]),
                   "r"(b[0]), "r"(b[1]));
}
__device__ __forceinline__ uint32_t pack_h2(float lo, float hi) {
    __half2 h = __floats2half2_rn(lo, hi);
    return *reinterpret_cast<uint32_t*>(&h);
}
__device__ __forceinline__ uint32_t ex2_h2(uint32_t a) {
    uint32_t d;
    asm("ex2.approx.f16x2 %0, %1;" : "=r"(d) : "r"(a));
    return d;
}
__device__ __forceinline__ void cpa16(uint32_t dst, const void* src) {
    asm volatile("cp.async.cg.shared.global [%0], [%1], 16;"
                 :: "r"(dst), "l"(src) : "memory");
}
#define CPA_COMMIT asm volatile("cp.async.commit_group;" ::: "memory")
#define CPA_WAIT2 asm volatile("cp.async.wait_group 2;" ::: "memory")
#define CPA_WAIT1 asm volatile("cp.async.wait_group 1;" ::: "memory")
#define CPA_WAIT0 asm volatile("cp.async.wait_group 0;" ::: "memory")

// ---------------------------------------------------------------------------
// One-time weight conversion: fp32 [k][n] -> fp16 hi/lo transposed [n][k]
// ---------------------------------------------------------------------------
__global__ __launch_bounds__(256) void conv_w(
    const float* __restrict__ wq, const float* __restrict__ wk,
    const float* __restrict__ wv, const float* __restrict__ wo)
{
    const int mat = blockIdx.y;
    const float* w = (mat == 0) ? wq : (mat == 1) ? wk : (mat == 2) ? wv : wo;
    int idx = blockIdx.x * 256 + threadIdx.x;
    int n = idx >> 8, k = idx & 255;
    float v = w[k * 256 + n];
    __half hi = __float2half_rn(v);
    g_w16h[mat * 65536 + idx] = hi;
    g_w16l[mat * 65536 + idx] = __float2half_rn(v - __half2float(hi));
}

// ---------------------------------------------------------------------------
// shared GEMM smem layout (192KB): X hi 64KB + 4 W chunk buffers x 32KB.
// 256 threads = 8 warps = 4 m-strips(32) x 2 n-halves(32).
// cp.async pipeline depth 3 (4-buffer ring).
// ---------------------------------------------------------------------------
#define GX_H 0
#define GW_B 65536
#define GEMM_SMEM 196608

#define BROW_OFF ((lane & 7) + ((lane & 16) >> 1))
#define BCOL_OFF ((lane & 8) << 1)

// W chunk: 64 n-rows x 128 k (k-half kh) -> 32KB chunk buffer (hi 16K + lo 16K)
__device__ __forceinline__ void load_w_chunk(uint32_t dst, const __half* wh,
                                             const __half* wl, int kh, int tid,
                                             bool with_lo) {
#pragma unroll
    for (int i = tid; i < 1024; i += 256) {
        int r = i >> 4, cp = i & 15;
        uint32_t so = (uint32_t)(cp >> 3) * 8192 +
                      swz128((uint32_t)(r * 128 + ((cp & 7) << 4)));
        int gof = r * 256 + (kh * 16 + cp) * 8;
        cpa16(dst + so, wh + gof);
        if (with_lo) cpa16(dst + 16384 + so, wl + gof);
    }
}

// ---------------------------------------------------------------------------
// Fused QKV projection. Q,K: single-term (x_hi x W_hi — error attenuated by
// softmax). V: 2-term (x_hi x (W_hi + W_lo) — passes straight to output).
// grid(128) x 256 threads. 24 chunks (z,nb,kh), depth-3 cp.async ring.
// ---------------------------------------------------------------------------
__global__ __launch_bounds__(256) void qkv_hmma(const float* __restrict__ x)
{
    extern __shared__ __align__(1024) char smem[];
    const int tid = threadIdx.x;
    const int wid = tid >> 5, lane = tid & 31;
    const int mi = wid & 3, ni = wid >> 2;
    const int m0 = blockIdx.x * 128;
    const uint32_t sb = smem_u32(smem);

    // prologue: chunks 0,1,2 (all z=0 -> no lo)
#pragma unroll
    for (int p = 0; p < 3; p++) {
        const int nb = (p >> 1) & 3, kh = p & 1;
        load_w_chunk(sb + GW_B + p * 32768,
                     g_w16h + nb * 64 * 256, g_w16l + nb * 64 * 256,
                     kh, tid, false);
        CPA_COMMIT;
    }

    // X tile: fp32 -> fp16 hi panels (once for all 3 matrices)
    for (int i = tid; i < 8192; i += 256) {
        int r = i >> 6;
        int kc = (i & 63) << 2;
        float4 v = *reinterpret_cast<const float4*>(x + (size_t)(m0 + r) * 256 + kc);
        uint32_t so = (uint32_t)(kc >> 6) * 16384 +
                      swz128((uint32_t)(r * 128 + (kc & 63) * 2));
        *(uint32_t*)(smem + GX_H + so)     = pack_h2(v.x, v.y);
        *(uint32_t*)(smem + GX_H + so + 4) = pack_h2(v.z, v.w);
    }

    const int b = m0 >> 11;
    const float QSCALE = 0.125f * 1.44269504f;   // 1/sqrt(64) * log2(e)

    float acc[2][4][4];   // [m strip][jl*2+e][frag]

    for (int c = 0; c < 24; c++) {
        const int z = c >> 3, nb = (c >> 1) & 3, kh = c & 1;
        if (c + 2 < 24) { CPA_WAIT2; }
        else if (c + 1 < 24) { CPA_WAIT1; }
        else { CPA_WAIT0; }
        __syncthreads();   // chunk c visible to all; compute(c-1) done

        if (c + 3 < 24) {
            const int c3 = c + 3;
            const int z3 = c3 >> 3, nb3 = (c3 >> 1) & 3, kh3 = c3 & 1;
            load_w_chunk(sb + GW_B + (c3 & 3) * 32768,
                         g_w16h + z3 * 65536 + nb3 * 64 * 256,
                         g_w16l + z3 * 65536 + nb3 * 64 * 256,
                         kh3, tid, z3 == 2);
            CPA_COMMIT;
        }

        if (kh == 0) {
#pragma unroll
            for (int st = 0; st < 2; st++)
#pragma unroll
                for (int j = 0; j < 4; j++)
#pragma unroll
                    for (int e = 0; e < 4; e++) acc[st][j][e] = 0.f;
        }

        const uint32_t wb = sb + GW_B + (c & 3) * 32768;
        const bool do_lo = (z == 2);
#pragma unroll
        for (int kk = 0; kk < 8; kk++) {
            const int kk2 = kh * 8 + kk;
            uint32_t ah[2][4];
#pragma unroll
            for (int st = 0; st < 2; st++) {
                uint32_t aoff = (uint32_t)(kk2 >> 2) * 16384 +
                    swz128((uint32_t)((mi * 32 + st * 16 + (lane & 15)) * 128 +
                                      (kk2 & 3) * 32 + (lane >> 4) * 16));
                ldsm_x4(ah[st], sb + GX_H + aoff);
            }
            uint32_t boffs[2];
#pragma unroll
            for (int jl = 0; jl < 2; jl++) {
                const int j = ni * 2 + jl;
                boffs[jl] = (uint32_t)(kk >> 2) * 8192 +
                    swz128((uint32_t)((16 * j + BROW_OFF) * 128 +
                                      (kk & 3) * 32 + BCOL_OFF));
            }
            uint32_t bh[2][4];
#pragma unroll
            for (int jl = 0; jl < 2; jl++) ldsm_x4(bh[jl], wb + boffs[jl]);
#pragma unroll
            for (int st = 0; st < 2; st++)
#pragma unroll
                for (int jl = 0; jl < 2; jl++) {
                    mma16816(acc[st][2 * jl], ah[st], bh[jl]);
                    mma16816(acc[st][2 * jl + 1], ah[st], bh[jl] + 2);
                }
            if (do_lo) {
                uint32_t bl[2][4];
#pragma unroll
                for (int jl = 0; jl < 2; jl++)
                    ldsm_x4(bl[jl], wb + 16384 + boffs[jl]);
#pragma unroll
                for (int st = 0; st < 2; st++)
#pragma unroll
                    for (int jl = 0; jl < 2; jl++) {
                        mma16816(acc[st][2 * jl], ah[st], bl[jl]);
                        mma16816(acc[st][2 * jl + 1], ah[st], bl[jl] + 2);
                    }
            }
        }

        if (kh == 1) {
            const int h = nb;
#pragma unroll
            for (int st = 0; st < 2; st++) {
                const int s0 = (m0 & 2047) + mi * 32 + st * 16 + (lane >> 2);
                if (z == 0) {
                    __half* q = g_q16h + ((size_t)(b * H_ + h) * S_) * DH_;
#pragma unroll
                    for (int jl = 0; jl < 2; jl++) {
                        int d = ni * 32 + jl * 16 + (lane & 3) * 2;
#pragma unroll
                        for (int e = 0; e < 2; e++) {
                            float* a = acc[st][2 * jl + e];
                            *(uint32_t*)&q[(size_t)s0 * DH_ + d + 8 * e] =
                                pack_h2(a[0] * QSCALE, a[1] * QSCALE);
                            *(uint32_t*)&q[(size_t)(s0 + 8) * DH_ + d + 8 * e] =
                                pack_h2(a[2] * QSCALE, a[3] * QSCALE);
                        }
                    }
                } else {
                    __half* dst = ((z == 1) ? g_k16h : g_v16h) +
                                  ((size_t)(b * H_ + h) * S_) * DH_;
#pragma unroll
                    for (int jl = 0; jl < 2; jl++) {
                        int d = ni * 32 + jl * 16 + (lane & 3) * 2;
#pragma unroll
                        for (int e = 0; e < 2; e++) {
                            float* a = acc[st][2 * jl + e];
                            *(uint32_t*)&dst[(size_t)s0 * DH_ + d + 8 * e] =
                                pack_h2(a[0], a[1]);
                            *(uint32_t*)&dst[(size_t)(s0 + 8) * DH_ + d + 8 * e] =
                                pack_h2(a[2], a[3]);
                        }
                    }
                }
            }
        }
    }
}

// ---------------------------------------------------------------------------
// Output projection. 2-term split: ctx_hi x (Wo_hi + Wo_lo).
// grid(128) x 256 threads, 8 chunks, depth-3 cp.async ring, 4m x 2n warps.
// ---------------------------------------------------------------------------
__global__ __launch_bounds__(256) void out_hmma(
    const float* __restrict__ bo, float* __restrict__ out)
{
    extern __shared__ __align__(1024) char smem[];
    const int tid = threadIdx.x;
    const int wid = tid >> 5, lane = tid & 31;
    const int mi = wid & 3, ni = wid >> 2;
    const int m0 = blockIdx.x * 128;
    const uint32_t sb = smem_u32(smem);

    const __half* wbh = g_w16h + 3 * 65536;
    const __half* wbl = g_w16l + 3 * 65536;

    // W chunk 0
    load_w_chunk(sb + GW_B, wbh, wbl, 0, tid, true);
    CPA_COMMIT;
    // ctx tile (fp16, 64KB)
    for (int i = tid; i < 4096; i += 256) {
        int r = i >> 5, c = i & 31;
        uint32_t so = (uint32_t)(c >> 3) * 16384 +
                      swz128((uint32_t)(r * 128 + ((c & 7) << 4)));
        cpa16(sb + GX_H + so, g_ctxh + (size_t)(m0 + r) * 256 + c * 8);
    }
    CPA_COMMIT;
    // W chunks 1,2
#pragma unroll
    for (int p = 1; p < 3; p++) {
        load_w_chunk(sb + GW_B + p * 32768,
                     wbh + ((p >> 1) & 3) * 64 * 256,
                     wbl + ((p >> 1) & 3) * 64 * 256, p & 1, tid, true);
        CPA_COMMIT;
    }

    float acc[2][4][4];

    for (int c = 0; c < 8; c++) {
        const int nb = c >> 1, kh = c & 1;
        if (c + 2 < 8) { CPA_WAIT2; }
        else if (c + 1 < 8) { CPA_WAIT1; }
        else { CPA_WAIT0; }
        __syncthreads();

        if (c + 3 < 8) {
            const int c3 = c + 3;
            load_w_chunk(sb + GW_B + (c3 & 3) * 32768,
                         wbh + ((c3 >> 1) & 3) * 64 * 256,
                         wbl + ((c3 >> 1) & 3) * 64 * 256, c3 & 1, tid, true);
            CPA_COMMIT;
        }

        if (kh == 0) {
#pragma unroll
            for (int st = 0; st < 2; st++)
#pragma unroll
                for (int j = 0; j < 4; j++)
#pragma unroll
                    for (int e = 0; e < 4; e++) acc[st][j][e] = 0.f;
        }

        const uint32_t wb = sb + GW_B + (c & 3) * 32768;
#pragma unroll
        for (int kk = 0; kk < 8; kk++) {
            const int kk2 = kh * 8 + kk;
            uint32_t ah[2][4];
#pragma unroll
            for (int st = 0; st < 2; st++) {
                uint32_t aoff = (uint32_t)(kk2 >> 2) * 16384 +
                    swz128((uint32_t)((mi * 32 + st * 16 + (lane & 15)) * 128 +
                                      (kk2 & 3) * 32 + (lane >> 4) * 16));
                ldsm_x4(ah[st], sb + GX_H + aoff);
            }
            uint32_t bh[2][4], bl[2][4];
#pragma unroll
            for (int jl = 0; jl < 2; jl++) {
                const int j = ni * 2 + jl;
                uint32_t boff = (uint32_t)(kk >> 2) * 8192 +
                    swz128((uint32_t)((16 * j + BROW_OFF) * 128 +
                                      (kk & 3) * 32 + BCOL_OFF));
                ldsm_x4(bh[jl], wb + boff);
                ldsm_x4(bl[jl], wb + 16384 + boff);
            }
#pragma unroll
            for (int st = 0; st < 2; st++)
#pragma unroll
                for (int jl = 0; jl < 2; jl++) {
                    mma16816(acc[st][2 * jl], ah[st], bh[jl]);
                    mma16816(acc[st][2 * jl + 1], ah[st], bh[jl] + 2);
                }
#pragma unroll
            for (int st = 0; st < 2; st++)
#pragma unroll
                for (int jl = 0; jl < 2; jl++) {
                    mma16816(acc[st][2 * jl], ah[st], bl[jl]);
                    mma16816(acc[st][2 * jl + 1], ah[st], bl[jl] + 2);
                }
        }

        if (kh == 1) {
#pragma unroll
            for (int st = 0; st < 2; st++) {
                const int row0 = m0 + mi * 32 + st * 16 + (lane >> 2);
#pragma unroll
                for (int jl = 0; jl < 2; jl++) {
#pragma unroll
                    for (int e = 0; e < 2; e++) {
                        int n = nb * 64 + ni * 32 + jl * 16 + 8 * e + (lane & 3) * 2;
                        float* a = acc[st][2 * jl + e];
                        float2 bias = *reinterpret_cast<const float2*>(bo + n);
                        float2 v0 = {a[0] + bias.x, a[1] + bias.y};
                        float2 v1 = {a[2] + bias.x, a[3] + bias.y};
                        *reinterpret_cast<float2*>(out + (size_t)row0 * 256 + n) = v0;
                        *reinterpret_cast<float2*>(out + (size_t)(row0 + 8) * 256 + n) = v1;
                    }
                }
            }
        }
    }
}

// ---------------------------------------------------------------------------
// fp16 HMMA flash attention (R11 exact — at HMMA/crossbar roofline, frozen).
// ---------------------------------------------------------------------------
#define MQ 128
#define NKV 128

#define QH_OFF 0            // 128 x 128B  (Q hi, fp16, scaled)
#define BUF_BASE 16384      // 2 buffers x 32KB
#define KBH 0               // K tile 16KB (128 kv x 128B)
#define VBH 16384           // V tile 16KB (128 kv x 128B)
#define BUF_SZ 32768
#define ATTN_SMEM (16384 + 2 * BUF_SZ)

__global__ __launch_bounds__(256, 2) void attn_kernel()
{
    extern __shared__ __align__(1024) char smem[];
    const int tid = threadIdx.x;
    const int wid = tid >> 5, lane = tid & 31;
    const int qt = blockIdx.x, h = blockIdx.y, b = blockIdx.z;
    const uint32_t sb = smem_u32(smem);

    const size_t hb = (size_t)(b * H_ + h);
    const char* qh  = (const char*)(g_q16h + (hb * S_ + (size_t)qt * MQ) * DH_);
    const char* kh0 = (const char*)(g_k16h + hb * S_ * DH_);
    const char* vh0 = (const char*)(g_v16h + hb * S_ * DH_);

    for (int i = tid; i < 1024; i += 256) {
        int r = i >> 3, c = (i & 7) << 4;
        uint32_t so = swz128((uint32_t)(r * 128 + c));
        *(float4*)(smem + QH_OFF + so) = *(const float4*)(qh + r * 128 + c);
    }

    const int kr = tid >> 3, kc = (tid & 7) << 4;

    auto prefetch = [&](int t, uint32_t bb) {
        const char* kh = kh0 + (size_t)t * 128 * 128;
        const char* vh = vh0 + (size_t)t * 128 * 128;
#pragma unroll
        for (int s = 0; s < 4; s++) {
            int r = kr + s * 32;
            uint32_t so = swz128((uint32_t)(r * 128 + kc));
            cpa16(bb + KBH + so, kh + r * 128 + kc);
            cpa16(bb + VBH + so, vh + r * 128 + kc);
        }
    };

    prefetch(0, sb + BUF_BASE);
    CPA_COMMIT;
    __syncthreads();

    const int mrow = wid * 16;
    uint32_t aqh[4][4];
#pragma unroll
    for (int kk = 0; kk < 4; kk++) {
        uint32_t off = swz128((uint32_t)((mrow + (lane & 15)) * 128 +
                                         kk * 32 + (lane >> 4) * 16));
        ldsm_x4(aqh[kk], sb + QH_OFF + off);
    }

    const int brow_off = BROW_OFF;
    const int bcol_off = BCOL_OFF;
    const int trow = (lane & 7) + ((lane >> 3) & 1) * 8;
    const int tcol = (lane >> 4) * 16;

    float o[8][4] = {};
    float lsum0 = 0.0f, lsum1 = 0.0f;
    int buf = 0;

    for (int t = 0; t < S_ / NKV; t++) {
        if (t + 1 < S_ / NKV) {
            prefetch(t + 1, sb + BUF_BASE + (buf ^ 1) * BUF_SZ);
            CPA_COMMIT;
            CPA_WAIT1;
        } else {
            CPA_WAIT0;
        }
        __syncthreads();

        const uint32_t bb = sb + BUF_BASE + buf * BUF_SZ;

        // ---- S(log2) = Q @ K^T; P = ex2(S) packed fp16 ----
        uint32_t ph[16][2];
#pragma unroll
        for (int j = 0; j < 8; j++) {
            float c0[4] = {0.f, 0.f, 0.f, 0.f};
            float c1[4] = {0.f, 0.f, 0.f, 0.f};
#pragma unroll
            for (int kk = 0; kk < 4; kk++) {
                uint32_t off = swz128((uint32_t)((16 * j + brow_off) * 128 +
                                                 kk * 32 + bcol_off));
                uint32_t bh[4];
                ldsm_x4(bh, bb + KBH + off);
                mma16816(c0, aqh[kk], bh);
                mma16816(c1, aqh[kk], bh + 2);
            }
#pragma unroll
            for (int half = 0; half < 2; half++) {
                float* c = half ? c1 : c0;
                uint32_t p01 = ex2_h2(pack_h2(c[0], c[1]));
                uint32_t p23 = ex2_h2(pack_h2(c[2], c[3]));
                float2 f01 = __half22float2(*reinterpret_cast<__half2*>(&p01));
                float2 f23 = __half22float2(*reinterpret_cast<__half2*>(&p23));
                lsum0 += f01.x + f01.y;
                lsum1 += f23.x + f23.y;
                ph[2 * j + half][0] = p01;
                ph[2 * j + half][1] = p23;
            }
        }

        // ---- O += P @ V (V row-major [kv][dh], trans ldsm) ----
#pragma unroll
        for (int kk = 0; kk < 8; kk++) {
            uint32_t ah[4] = {ph[2 * kk][0], ph[2 * kk][1],
                              ph[2 * kk + 1][0], ph[2 * kk + 1][1]};
#pragma unroll
            for (int n = 0; n < 4; n++) {
                uint32_t off = swz128((uint32_t)((16 * kk + trow) * 128 +
                                                 n * 32 + tcol));
                uint32_t bh[4];
                ldsm_x4t(bh, bb + VBH + off);
                mma16816(o[2 * n], ah, bh);
                mma16816(o[2 * n + 1], ah, bh + 2);
            }
        }

        __syncthreads();
        buf ^= 1;
    }

    lsum0 += __shfl_xor_sync(0xffffffffu, lsum0, 1);
    lsum0 += __shfl_xor_sync(0xffffffffu, lsum0, 2);
    lsum1 += __shfl_xor_sync(0xffffffffu, lsum1, 1);
    lsum1 += __shfl_xor_sync(0xffffffffu, lsum1, 2);
    const float inv0 = 1.0f / lsum0;
    const float inv1 = 1.0f / lsum1;

    const int r0 = qt * MQ + mrow + (lane >> 2);
    size_t base0 = ((size_t)(b * S_ + r0)) * D_ + h * DH_ + (lane & 3) * 2;
    size_t base1 = base0 + 8 * D_;
#pragma unroll
    for (int n = 0; n < 8; n++) {
        *(uint32_t*)&g_ctxh[base0 + 8 * n] =
            pack_h2(o[n][0] * inv0, o[n][1] * inv0);
        *(uint32_t*)&g_ctxh[base1 + 8 * n] =
            pack_h2(o[n][2] * inv1, o[n][3] * inv1);
    }
}

// ---------------------------------------------------------------------------
extern "C" void kernel_launch(void* const* d_in, const int* in_sizes, int n_in,
                              void* d_out, int out_size)
{
    (void)in_sizes; (void)n_in; (void)out_size;
    const float* x  = (const float*)d_in[0];
    const float* wq = (const float*)d_in[1];
    const float* wk = (const float*)d_in[2];
    const float* wv = (const float*)d_in[3];
    const float* wo = (const float*)d_in[4];
    const float* bo = (const float*)d_in[5];
    float* out = (float*)d_out;

    cudaFuncSetAttribute(attn_kernel,
                         cudaFuncAttributeMaxDynamicSharedMemorySize, ATTN_SMEM);
    cudaFuncSetAttribute(qkv_hmma,
                         cudaFuncAttributeMaxDynamicSharedMemorySize, GEMM_SMEM);
    cudaFuncSetAttribute(out_hmma,
                         cudaFuncAttributeMaxDynamicSharedMemorySize, GEMM_SMEM);

    dim3 gc(256, 4);
    conv_w<<<gc, 256>>>(wq, wk, wv, wo);

    qkv_hmma<<<128, 256, GEMM_SMEM>>>(x);

    dim3 g2(S_ / MQ, H_, B_);
    attn_kernel<<<g2, 256, ATTN_SMEM>>>();

    out_hmma<<<128, 256, GEMM_SMEM>>>(bo, out);
}

// round 17
// speedup vs baseline: 1.5382x; 1.5382x over previous
#include <cuda_runtime.h>
#include <cuda_fp16.h>
#include <cstdint>
#include <math.h>

#define B_ 8
#define S_ 2048
#define D_ 256
#define H_ 4
#define DH_ 64

#define QKV_ELEMS ((size_t)B_ * H_ * S_ * DH_)
#define CTX_ELEMS ((size_t)B_ * S_ * D_)

// Scratch (allocation-free rule: __device__ globals)
__device__ __half g_q16h[QKV_ELEMS];   // [b,h,s,dh], pre-scaled by log2e/8
__device__ __half g_k16h[QKV_ELEMS];   // [b,h,s,dh]
__device__ __half g_v16h[QKV_ELEMS];   // [b,h,s,dh]  (ldsm.trans in attention)
__device__ __half g_ctxh[CTX_ELEMS];   // [b*s, 256]  (single fp16)
__device__ __half g_w16h[4 * 256 * 256];  // [mat][n][k] transposed, mats: q,k,v,o
__device__ __half g_w16l[4 * 256 * 256];

// ---------------------------------------------------------------------------
// helpers
// ---------------------------------------------------------------------------
__device__ __forceinline__ uint32_t smem_u32(const void* p) {
    uint32_t a;
    asm("{ .reg .u64 t; cvta.to.shared.u64 t, %1; cvt.u32.u64 %0, t; }"
        : "=r"(a) : "l"(p));
    return a;
}
__device__ __forceinline__ uint32_t swz128(uint32_t x) {
    return x ^ ((x >> 3) & 0x70);
}
__device__ __forceinline__ void ldsm_x4(uint32_t* r, uint32_t addr) {
    asm volatile("ldmatrix.sync.aligned.m8n8.x4.shared.b16 {%0,%1,%2,%3}, [%4];"
                 : "=r"(r[0]), "=r"(r[1]), "=r"(r[2]), "=r"(r[3]) : "r"(addr));
}
__device__ __forceinline__ void ldsm_x4t(uint32_t* r, uint32_t addr) {
    asm volatile("ldmatrix.sync.aligned.m8n8.x4.trans.shared.b16 {%0,%1,%2,%3}, [%4];"
                 : "=r"(r[0]), "=r"(r[1]), "=r"(r[2]), "=r"(r[3]) : "r"(addr));
}
__device__ __forceinline__ void mma16816(float* c, const uint32_t* a, const uint32_t* b) {
    asm volatile("mma.sync.aligned.m16n8k16.row.col.f32.f16.f16.f32 "
                 "{%0,%1,%2,%3}, {%4,%5,%6,%7}, {%8,%9}, {%0,%1,%2,%3};"
                 : "+f"(c[0]), "+f"(c[1]), "+f"(c[2]), "+f"(c[3])
                 : "r"(a[0]), "r"(a[1]), "r"(a[2]), "r"(a[3]),
                   "r"(b[0]), "r"(b[1]));
}
__device__ __forceinline__ uint32_t pack_h2(float lo, float hi) {
    __half2 h = __floats2half2_rn(lo, hi);
    return *reinterpret_cast<uint32_t*>(&h);
}
__device__ __forceinline__ uint32_t ex2_h2(uint32_t a) {
    uint32_t d;
    asm("ex2.approx.f16x2 %0, %1;" : "=r"(d) : "r"(a));
    return d;
}
__device__ __forceinline__ void cpa16(uint32_t dst, const void* src) {
    asm volatile("cp.async.cg.shared.global [%0], [%1], 16;"
                 :: "r"(dst), "l"(src) : "memory");
}
#define CPA_COMMIT asm volatile("cp.async.commit_group;" ::: "memory")
#define CPA_WAIT2 asm volatile("cp.async.wait_group 2;" ::: "memory")
#define CPA_WAIT1 asm volatile("cp.async.wait_group 1;" ::: "memory")
#define CPA_WAIT0 asm volatile("cp.async.wait_group 0;" ::: "memory")

// ---------------------------------------------------------------------------
// One-time weight conversion: fp32 [k][n] -> fp16 hi/lo transposed [n][k]
// ---------------------------------------------------------------------------
__global__ __launch_bounds__(256) void conv_w(
    const float* __restrict__ wq, const float* __restrict__ wk,
    const float* __restrict__ wv, const float* __restrict__ wo)
{
    const int mat = blockIdx.y;
    const float* w = (mat == 0) ? wq : (mat == 1) ? wk : (mat == 2) ? wv : wo;
    int idx = blockIdx.x * 256 + threadIdx.x;
    int n = idx >> 8, k = idx & 255;
    float v = w[k * 256 + n];
    __half hi = __float2half_rn(v);
    g_w16h[mat * 65536 + idx] = hi;
    g_w16l[mat * 65536 + idx] = __float2half_rn(v - __half2float(hi));
}

// ---------------------------------------------------------------------------
// shared GEMM smem layout (192KB): X hi 64KB + 4 W chunk buffers x 32KB.
// 256 threads = 8 warps = 4 m-strips(32) x 2 n-halves(32).
// cp.async pipeline depth 3 (4-buffer ring).
// ---------------------------------------------------------------------------
#define GX_H 0
#define GW_B 65536
#define GEMM_SMEM 196608

#define BROW_OFF ((lane & 7) + ((lane & 16) >> 1))
#define BCOL_OFF ((lane & 8) << 1)

// W chunk: 64 n-rows x 128 k (k-half kh) -> 32KB chunk buffer (hi 16K [+ lo 16K])
__device__ __forceinline__ void load_w_chunk(uint32_t dst, const __half* wh,
                                             const __half* wl, int kh, int tid,
                                             bool with_lo) {
#pragma unroll
    for (int i = tid; i < 1024; i += 256) {
        int r = i >> 4, cp = i & 15;
        uint32_t so = (uint32_t)(cp >> 3) * 8192 +
                      swz128((uint32_t)(r * 128 + ((cp & 7) << 4)));
        int gof = r * 256 + (kh * 16 + cp) * 8;
        cpa16(dst + so, wh + gof);
        if (with_lo) cpa16(dst + 16384 + so, wl + gof);
    }
}

// issue prefetch for qkv chunk index c (0..23): z = c>>3 (lo only for z==2)
__device__ __forceinline__ void qkv_prefetch(uint32_t sb, int c, int tid) {
    const int z = c >> 3, nb = (c >> 1) & 3, kh = c & 1;
    load_w_chunk(sb + GW_B + (c & 3) * 32768,
                 g_w16h + z * 65536 + nb * 64 * 256,
                 g_w16l + z * 65536 + nb * 64 * 256, kh, tid, z == 2);
    CPA_COMMIT;
}

// ---------------------------------------------------------------------------
// Fused QKV projection. Q,K: single-term (x_hi x W_hi — error attenuated by
// softmax). V: 2-term (x_hi x (W_hi + W_lo)). Static phase split: chunks
// 0..15 (Q,K) use the no-lo body; 16..23 (V) use the 2-term body.
// grid(128) x 256 threads, depth-3 cp.async ring.
// ---------------------------------------------------------------------------
__global__ __launch_bounds__(256) void qkv_hmma(const float* __restrict__ x)
{
    extern __shared__ __align__(1024) char smem[];
    const int tid = threadIdx.x;
    const int wid = tid >> 5, lane = tid & 31;
    const int mi = wid & 3, ni = wid >> 2;
    const int m0 = blockIdx.x * 128;
    const uint32_t sb = smem_u32(smem);

    // prologue: chunks 0,1,2 in flight
    qkv_prefetch(sb, 0, tid);
    qkv_prefetch(sb, 1, tid);
    qkv_prefetch(sb, 2, tid);

    // X tile: fp32 -> fp16 hi panels (once for all 3 matrices)
    for (int i = tid; i < 8192; i += 256) {
        int r = i >> 6;
        int kc = (i & 63) << 2;
        float4 v = *reinterpret_cast<const float4*>(x + (size_t)(m0 + r) * 256 + kc);
        uint32_t so = (uint32_t)(kc >> 6) * 16384 +
                      swz128((uint32_t)(r * 128 + (kc & 63) * 2));
        *(uint32_t*)(smem + GX_H + so)     = pack_h2(v.x, v.y);
        *(uint32_t*)(smem + GX_H + so + 4) = pack_h2(v.z, v.w);
    }

    const int b = m0 >> 11;
    const float QSCALE = 0.125f * 1.44269504f;   // 1/sqrt(64) * log2(e)

    float acc[2][4][4];   // [m strip][jl*2+e][frag]

    // ---------------- phase A: chunks 0..15 (Q then K), single-term --------
    for (int c = 0; c < 16; c++) {
        const int z = c >> 3, nb = (c >> 1) & 3, kh = c & 1;
        CPA_WAIT2;
        __syncthreads();
        qkv_prefetch(sb, c + 3, tid);   // c+3 <= 18 < 24 always here

        if (kh == 0) {
#pragma unroll
            for (int st = 0; st < 2; st++)
#pragma unroll
                for (int j = 0; j < 4; j++)
#pragma unroll
                    for (int e = 0; e < 4; e++) acc[st][j][e] = 0.f;
        }

        const uint32_t wb = sb + GW_B + (c & 3) * 32768;
#pragma unroll
        for (int kk = 0; kk < 8; kk++) {
            const int kk2 = kh * 8 + kk;
            uint32_t ah[2][4];
#pragma unroll
            for (int st = 0; st < 2; st++) {
                uint32_t aoff = (uint32_t)(kk2 >> 2) * 16384 +
                    swz128((uint32_t)((mi * 32 + st * 16 + (lane & 15)) * 128 +
                                      (kk2 & 3) * 32 + (lane >> 4) * 16));
                ldsm_x4(ah[st], sb + GX_H + aoff);
            }
            uint32_t bh[2][4];
#pragma unroll
            for (int jl = 0; jl < 2; jl++) {
                const int j = ni * 2 + jl;
                uint32_t boff = (uint32_t)(kk >> 2) * 8192 +
                    swz128((uint32_t)((16 * j + BROW_OFF) * 128 +
                                      (kk & 3) * 32 + BCOL_OFF));
                ldsm_x4(bh[jl], wb + boff);
            }
#pragma unroll
            for (int st = 0; st < 2; st++)
#pragma unroll
                for (int jl = 0; jl < 2; jl++) {
                    mma16816(acc[st][2 * jl], ah[st], bh[jl]);
                    mma16816(acc[st][2 * jl + 1], ah[st], bh[jl] + 2);
                }
        }

        if (kh == 1) {
            const int h = nb;
            __half* dst = (z == 0) ? g_q16h : g_k16h;
            const float sc = (z == 0) ? QSCALE : 1.0f;
            dst += ((size_t)(b * H_ + h) * S_) * DH_;
#pragma unroll
            for (int st = 0; st < 2; st++) {
                const int s0 = (m0 & 2047) + mi * 32 + st * 16 + (lane >> 2);
#pragma unroll
                for (int jl = 0; jl < 2; jl++) {
                    int d = ni * 32 + jl * 16 + (lane & 3) * 2;
#pragma unroll
                    for (int e = 0; e < 2; e++) {
                        float* a = acc[st][2 * jl + e];
                        *(uint32_t*)&dst[(size_t)s0 * DH_ + d + 8 * e] =
                            pack_h2(a[0] * sc, a[1] * sc);
                        *(uint32_t*)&dst[(size_t)(s0 + 8) * DH_ + d + 8 * e] =
                            pack_h2(a[2] * sc, a[3] * sc);
                    }
                }
            }
        }
    }

    // ---------------- phase B: chunks 16..23 (V), 2-term --------------------
    for (int c = 16; c < 24; c++) {
        const int nb = (c >> 1) & 3, kh = c & 1;
        if (c + 2 < 24) { CPA_WAIT2; }
        else if (c + 1 < 24) { CPA_WAIT1; }
        else { CPA_WAIT0; }
        __syncthreads();
        if (c + 3 < 24) qkv_prefetch(sb, c + 3, tid);

        if (kh == 0) {
#pragma unroll
            for (int st = 0; st < 2; st++)
#pragma unroll
                for (int j = 0; j < 4; j++)
#pragma unroll
                    for (int e = 0; e < 4; e++) acc[st][j][e] = 0.f;
        }

        const uint32_t wb = sb + GW_B + (c & 3) * 32768;
#pragma unroll
        for (int kk = 0; kk < 8; kk++) {
            const int kk2 = kh * 8 + kk;
            uint32_t ah[2][4];
#pragma unroll
            for (int st = 0; st < 2; st++) {
                uint32_t aoff = (uint32_t)(kk2 >> 2) * 16384 +
                    swz128((uint32_t)((mi * 32 + st * 16 + (lane & 15)) * 128 +
                                      (kk2 & 3) * 32 + (lane >> 4) * 16));
                ldsm_x4(ah[st], sb + GX_H + aoff);
            }
            uint32_t bh[2][4], bl[2][4];
#pragma unroll
            for (int jl = 0; jl < 2; jl++) {
                const int j = ni * 2 + jl;
                uint32_t boff = (uint32_t)(kk >> 2) * 8192 +
                    swz128((uint32_t)((16 * j + BROW_OFF) * 128 +
                                      (kk & 3) * 32 + BCOL_OFF));
                ldsm_x4(bh[jl], wb + boff);
                ldsm_x4(bl[jl], wb + 16384 + boff);
            }
#pragma unroll
            for (int st = 0; st < 2; st++)
#pragma unroll
                for (int jl = 0; jl < 2; jl++) {
                    mma16816(acc[st][2 * jl], ah[st], bh[jl]);
                    mma16816(acc[st][2 * jl + 1], ah[st], bh[jl] + 2);
                }
#pragma unroll
            for (int st = 0; st < 2; st++)
#pragma unroll
                for (int jl = 0; jl < 2; jl++) {
                    mma16816(acc[st][2 * jl], ah[st], bl[jl]);
                    mma16816(acc[st][2 * jl + 1], ah[st], bl[jl] + 2);
                }
        }

        if (kh == 1) {
            __half* dst = g_v16h + ((size_t)(b * H_ + nb) * S_) * DH_;
#pragma unroll
            for (int st = 0; st < 2; st++) {
                const int s0 = (m0 & 2047) + mi * 32 + st * 16 + (lane >> 2);
#pragma unroll
                for (int jl = 0; jl < 2; jl++) {
                    int d = ni * 32 + jl * 16 + (lane & 3) * 2;
#pragma unroll
                    for (int e = 0; e < 2; e++) {
                        float* a = acc[st][2 * jl + e];
                        *(uint32_t*)&dst[(size_t)s0 * DH_ + d + 8 * e] =
                            pack_h2(a[0], a[1]);
                        *(uint32_t*)&dst[(size_t)(s0 + 8) * DH_ + d + 8 * e] =
                            pack_h2(a[2], a[3]);
                    }
                }
            }
        }
    }
}

// ---------------------------------------------------------------------------
// Output projection. 2-term split: ctx_hi x (Wo_hi + Wo_lo).
// grid(128) x 256 threads, 8 chunks, depth-3 cp.async ring, 4m x 2n warps.
// ---------------------------------------------------------------------------
__global__ __launch_bounds__(256) void out_hmma(
    const float* __restrict__ bo, float* __restrict__ out)
{
    extern __shared__ __align__(1024) char smem[];
    const int tid = threadIdx.x;
    const int wid = tid >> 5, lane = tid & 31;
    const int mi = wid & 3, ni = wid >> 2;
    const int m0 = blockIdx.x * 128;
    const uint32_t sb = smem_u32(smem);

    const __half* wbh = g_w16h + 3 * 65536;
    const __half* wbl = g_w16l + 3 * 65536;

    // W chunk 0
    load_w_chunk(sb + GW_B, wbh, wbl, 0, tid, true);
    CPA_COMMIT;
    // ctx tile (fp16, 64KB)
    for (int i = tid; i < 4096; i += 256) {
        int r = i >> 5, c = i & 31;
        uint32_t so = (uint32_t)(c >> 3) * 16384 +
                      swz128((uint32_t)(r * 128 + ((c & 7) << 4)));
        cpa16(sb + GX_H + so, g_ctxh + (size_t)(m0 + r) * 256 + c * 8);
    }
    CPA_COMMIT;
    // W chunks 1,2
#pragma unroll
    for (int p = 1; p < 3; p++) {
        load_w_chunk(sb + GW_B + p * 32768,
                     wbh + ((p >> 1) & 3) * 64 * 256,
                     wbl + ((p >> 1) & 3) * 64 * 256, p & 1, tid, true);
        CPA_COMMIT;
    }

    float acc[2][4][4];

    for (int c = 0; c < 8; c++) {
        const int nb = c >> 1, kh = c & 1;
        if (c + 2 < 8) { CPA_WAIT2; }
        else if (c + 1 < 8) { CPA_WAIT1; }
        else { CPA_WAIT0; }
        __syncthreads();

        if (c + 3 < 8) {
            const int c3 = c + 3;
            load_w_chunk(sb + GW_B + (c3 & 3) * 32768,
                         wbh + ((c3 >> 1) & 3) * 64 * 256,
                         wbl + ((c3 >> 1) & 3) * 64 * 256, c3 & 1, tid, true);
            CPA_COMMIT;
        }

        if (kh == 0) {
#pragma unroll
            for (int st = 0; st < 2; st++)
#pragma unroll
                for (int j = 0; j < 4; j++)
#pragma unroll
                    for (int e = 0; e < 4; e++) acc[st][j][e] = 0.f;
        }

        const uint32_t wb = sb + GW_B + (c & 3) * 32768;
#pragma unroll
        for (int kk = 0; kk < 8; kk++) {
            const int kk2 = kh * 8 + kk;
            uint32_t ah[2][4];
#pragma unroll
            for (int st = 0; st < 2; st++) {
                uint32_t aoff = (uint32_t)(kk2 >> 2) * 16384 +
                    swz128((uint32_t)((mi * 32 + st * 16 + (lane & 15)) * 128 +
                                      (kk2 & 3) * 32 + (lane >> 4) * 16));
                ldsm_x4(ah[st], sb + GX_H + aoff);
            }
            uint32_t bh[2][4], bl[2][4];
#pragma unroll
            for (int jl = 0; jl < 2; jl++) {
                const int j = ni * 2 + jl;
                uint32_t boff = (uint32_t)(kk >> 2) * 8192 +
                    swz128((uint32_t)((16 * j + BROW_OFF) * 128 +
                                      (kk & 3) * 32 + BCOL_OFF));
                ldsm_x4(bh[jl], wb + boff);
                ldsm_x4(bl[jl], wb + 16384 + boff);
            }
#pragma unroll
            for (int st = 0; st < 2; st++)
#pragma unroll
                for (int jl = 0; jl < 2; jl++) {
                    mma16816(acc[st][2 * jl], ah[st], bh[jl]);
                    mma16816(acc[st][2 * jl + 1], ah[st], bh[jl] + 2);
                }
#pragma unroll
            for (int st = 0; st < 2; st++)
#pragma unroll
                for (int jl = 0; jl < 2; jl++) {
                    mma16816(acc[st][2 * jl], ah[st], bl[jl]);
                    mma16816(acc[st][2 * jl + 1], ah[st], bl[jl] + 2);
                }
        }

        if (kh == 1) {
#pragma unroll
            for (int st = 0; st < 2; st++) {
                const int row0 = m0 + mi * 32 + st * 16 + (lane >> 2);
#pragma unroll
                for (int jl = 0; jl < 2; jl++) {
#pragma unroll
                    for (int e = 0; e < 2; e++) {
                        int n = nb * 64 + ni * 32 + jl * 16 + 8 * e + (lane & 3) * 2;
                        float* a = acc[st][2 * jl + e];
                        float2 bias = *reinterpret_cast<const float2*>(bo + n);
                        float2 v0 = {a[0] + bias.x, a[1] + bias.y};
                        float2 v1 = {a[2] + bias.x, a[3] + bias.y};
                        *reinterpret_cast<float2*>(out + (size_t)row0 * 256 + n) = v0;
                        *reinterpret_cast<float2*>(out + (size_t)(row0 + 8) * 256 + n) = v1;
                    }
                }
            }
        }
    }
}

// ---------------------------------------------------------------------------
// fp16 HMMA flash attention (R11 exact — at HMMA/crossbar roofline, frozen).
// ---------------------------------------------------------------------------
#define MQ 128
#define NKV 128

#define QH_OFF 0            // 128 x 128B  (Q hi, fp16, scaled)
#define BUF_BASE 16384      // 2 buffers x 32KB
#define KBH 0               // K tile 16KB (128 kv x 128B)
#define VBH 16384           // V tile 16KB (128 kv x 128B)
#define BUF_SZ 32768
#define ATTN_SMEM (16384 + 2 * BUF_SZ)

__global__ __launch_bounds__(256, 2) void attn_kernel()
{
    extern __shared__ __align__(1024) char smem[];
    const int tid = threadIdx.x;
    const int wid = tid >> 5, lane = tid & 31;
    const int qt = blockIdx.x, h = blockIdx.y, b = blockIdx.z;
    const uint32_t sb = smem_u32(smem);

    const size_t hb = (size_t)(b * H_ + h);
    const char* qh  = (const char*)(g_q16h + (hb * S_ + (size_t)qt * MQ) * DH_);
    const char* kh0 = (const char*)(g_k16h + hb * S_ * DH_);
    const char* vh0 = (const char*)(g_v16h + hb * S_ * DH_);

    for (int i = tid; i < 1024; i += 256) {
        int r = i >> 3, c = (i & 7) << 4;
        uint32_t so = swz128((uint32_t)(r * 128 + c));
        *(float4*)(smem + QH_OFF + so) = *(const float4*)(qh + r * 128 + c);
    }

    const int kr = tid >> 3, kc = (tid & 7) << 4;

    auto prefetch = [&](int t, uint32_t bb) {
        const char* kh = kh0 + (size_t)t * 128 * 128;
        const char* vh = vh0 + (size_t)t * 128 * 128;
#pragma unroll
        for (int s = 0; s < 4; s++) {
            int r = kr + s * 32;
            uint32_t so = swz128((uint32_t)(r * 128 + kc));
            cpa16(bb + KBH + so, kh + r * 128 + kc);
            cpa16(bb + VBH + so, vh + r * 128 + kc);
        }
    };

    prefetch(0, sb + BUF_BASE);
    CPA_COMMIT;
    __syncthreads();

    const int mrow = wid * 16;
    uint32_t aqh[4][4];
#pragma unroll
    for (int kk = 0; kk < 4; kk++) {
        uint32_t off = swz128((uint32_t)((mrow + (lane & 15)) * 128 +
                                         kk * 32 + (lane >> 4) * 16));
        ldsm_x4(aqh[kk], sb + QH_OFF + off);
    }

    const int brow_off = BROW_OFF;
    const int bcol_off = BCOL_OFF;
    const int trow = (lane & 7) + ((lane >> 3) & 1) * 8;
    const int tcol = (lane >> 4) * 16;

    float o[8][4] = {};
    float lsum0 = 0.0f, lsum1 = 0.0f;
    int buf = 0;

    for (int t = 0; t < S_ / NKV; t++) {
        if (t + 1 < S_ / NKV) {
            prefetch(t + 1, sb + BUF_BASE + (buf ^ 1) * BUF_SZ);
            CPA_COMMIT;
            CPA_WAIT1;
        } else {
            CPA_WAIT0;
        }
        __syncthreads();

        const uint32_t bb = sb + BUF_BASE + buf * BUF_SZ;

        // ---- S(log2) = Q @ K^T; P = ex2(S) packed fp16 ----
        uint32_t ph[16][2];
#pragma unroll
        for (int j = 0; j < 8; j++) {
            float c0[4] = {0.f, 0.f, 0.f, 0.f};
            float c1[4] = {0.f, 0.f, 0.f, 0.f};
#pragma unroll
            for (int kk = 0; kk < 4; kk++) {
                uint32_t off = swz128((uint32_t)((16 * j + brow_off) * 128 +
                                                 kk * 32 + bcol_off));
                uint32_t bh[4];
                ldsm_x4(bh, bb + KBH + off);
                mma16816(c0, aqh[kk], bh);
                mma16816(c1, aqh[kk], bh + 2);
            }
#pragma unroll
            for (int half = 0; half < 2; half++) {
                float* c = half ? c1 : c0;
                uint32_t p01 = ex2_h2(pack_h2(c[0], c[1]));
                uint32_t p23 = ex2_h2(pack_h2(c[2], c[3]));
                float2 f01 = __half22float2(*reinterpret_cast<__half2*>(&p01));
                float2 f23 = __half22float2(*reinterpret_cast<__half2*>(&p23));
                lsum0 += f01.x + f01.y;
                lsum1 += f23.x + f23.y;
                ph[2 * j + half][0] = p01;
                ph[2 * j + half][1] = p23;
            }
        }

        // ---- O += P @ V (V row-major [kv][dh], trans ldsm) ----
#pragma unroll
        for (int kk = 0; kk < 8; kk++) {
            uint32_t ah[4] = {ph[2 * kk][0], ph[2 * kk][1],
                              ph[2 * kk + 1][0], ph[2 * kk + 1][1]};
#pragma unroll
            for (int n = 0; n < 4; n++) {
                uint32_t off = swz128((uint32_t)((16 * kk + trow) * 128 +
                                                 n * 32 + tcol));
                uint32_t bh[4];
                ldsm_x4t(bh, bb + VBH + off);
                mma16816(o[2 * n], ah, bh);
                mma16816(o[2 * n + 1], ah, bh + 2);
            }
        }

        __syncthreads();
        buf ^= 1;
    }

    lsum0 += __shfl_xor_sync(0xffffffffu, lsum0, 1);
    lsum0 += __shfl_xor_sync(0xffffffffu, lsum0, 2);
    lsum1 += __shfl_xor_sync(0xffffffffu, lsum1, 1);
    lsum1 += __shfl_xor_sync(0xffffffffu, lsum1, 2);
    const float inv0 = 1.0f / lsum0;
    const float inv1 = 1.0f / lsum1;

    const int r0 = qt * MQ + mrow + (lane >> 2);
    size_t base0 = ((size_t)(b * S_ + r0)) * D_ + h * DH_ + (lane & 3) * 2;
    size_t base1 = base0 + 8 * D_;
#pragma unroll
    for (int n = 0; n < 8; n++) {
        *(uint32_t*)&g_ctxh[base0 + 8 * n] =
            pack_h2(o[n][0] * inv0, o[n][1] * inv0);
        *(uint32_t*)&g_ctxh[base1 + 8 * n] =
            pack_h2(o[n][2] * inv1, o[n][3] * inv1);
    }
}

// ---------------------------------------------------------------------------
extern "C" void kernel_launch(void* const* d_in, const int* in_sizes, int n_in,
                              void* d_out, int out_size)
{
    (void)in_sizes; (void)n_in; (void)out_size;
    const float* x  = (const float*)d_in[0];
    const float* wq = (const float*)d_in[1];
    const float* wk = (const float*)d_in[2];
    const float* wv = (const float*)d_in[3];
    const float* wo = (const float*)d_in[4];
    const float* bo = (const float*)d_in[5];
    float* out = (float*)d_out;

    cudaFuncSetAttribute(attn_kernel,
                         cudaFuncAttributeMaxDynamicSharedMemorySize, ATTN_SMEM);
    cudaFuncSetAttribute(qkv_hmma,
                         cudaFuncAttributeMaxDynamicSharedMemorySize, GEMM_SMEM);
    cudaFuncSetAttribute(out_hmma,
                         cudaFuncAttributeMaxDynamicSharedMemorySize, GEMM_SMEM);

    dim3 gc(256, 4);
    conv_w<<<gc, 256>>>(wq, wk, wv, wo);

    qkv_hmma<<<128, 256, GEMM_SMEM>>>(x);

    dim3 g2(S_ / MQ, H_, B_);
    attn_kernel<<<g2, 256, ATTN_SMEM>>>();

    out_hmma<<<128, 256, GEMM_SMEM>>>(bo, out);
}